// round 1
// baseline (speedup 1.0000x reference)
#include <cuda_runtime.h>

// ---------------- problem constants ----------------
#define BB 64
#define NN 64
#define DD 512
#define TSTEPS 32
#define CCH 16
#define KKW 5
#define HH 128
#define WW 128

// ---------------- device scratch (static, no allocs) ----------------
__device__ float g_k[BB*NN*DD];          // 8 MB
__device__ float g_v[BB*NN*DD];          // 8 MB
__device__ float g_s[2][BB*DD];
__device__ float g_r[BB*DD];
__device__ float g_qpart[8][BB*DD];      // q split-K parts
__device__ float g_gipart[16][BB*1536];  // gi split-K parts
__device__ float g_ghpart[8][BB*1536];   // gh split-K parts
__device__ float g_ppart[16][BB*448];    // patch parts (N padded 400->448)
__device__ int   g_ij[BB*2];             // (i,j) per batch

__device__ __forceinline__ float4 ld4(const float* p){ return *reinterpret_cast<const float4*>(p); }

// ---------------- 64x64 tile GEMM core, KC=64, 64 threads, 8x8 per thread --
// C[64 rows, 64 cols] = A[64, k0..k0+64) @ W[n0.., k0..k0+64)^T  (no bias)
__device__ __forceinline__ void gemm64_kc64(
    const float* __restrict__ Ab, int lda,      // Ab = &A[0*lda + k0]
    const float* __restrict__ Wb, int ldw,      // Wb = &W[(n0+0)*ldw + k0]
    float* __restrict__ Cb, int ldc,            // Cb = &C[0*ldc + n0]
    int nvalid)                                  // valid cols in tile
{
    __shared__ float sA[16][64];
    __shared__ float sW[16][64];
    float acc[8][8];
#pragma unroll
    for (int i=0;i<8;i++)
#pragma unroll
        for (int j=0;j<8;j++) acc[i][j]=0.f;

    const int t  = threadIdx.x;
    const int r0 = (t>>3)<<3;
    const int c0 = (t&7)<<3;

    for (int kc=0; kc<64; kc+=16){
        const float* ap = Ab + t*lda + kc;
        float4 a0=ld4(ap), a1=ld4(ap+4), a2=ld4(ap+8), a3=ld4(ap+12);
        float4 w0,w1,w2,w3;
        if (t < nvalid){
            const float* wp = Wb + t*ldw + kc;
            w0=ld4(wp); w1=ld4(wp+4); w2=ld4(wp+8); w3=ld4(wp+12);
        } else {
            w0=make_float4(0,0,0,0); w1=w0; w2=w0; w3=w0;
        }
        __syncthreads();
        sA[ 0][t]=a0.x; sA[ 1][t]=a0.y; sA[ 2][t]=a0.z; sA[ 3][t]=a0.w;
        sA[ 4][t]=a1.x; sA[ 5][t]=a1.y; sA[ 6][t]=a1.z; sA[ 7][t]=a1.w;
        sA[ 8][t]=a2.x; sA[ 9][t]=a2.y; sA[10][t]=a2.z; sA[11][t]=a2.w;
        sA[12][t]=a3.x; sA[13][t]=a3.y; sA[14][t]=a3.z; sA[15][t]=a3.w;
        sW[ 0][t]=w0.x; sW[ 1][t]=w0.y; sW[ 2][t]=w0.z; sW[ 3][t]=w0.w;
        sW[ 4][t]=w1.x; sW[ 5][t]=w1.y; sW[ 6][t]=w1.z; sW[ 7][t]=w1.w;
        sW[ 8][t]=w2.x; sW[ 9][t]=w2.y; sW[10][t]=w2.z; sW[11][t]=w2.w;
        sW[12][t]=w3.x; sW[13][t]=w3.y; sW[14][t]=w3.z; sW[15][t]=w3.w;
        __syncthreads();
#pragma unroll
        for (int k=0;k<16;k++){
            float4 x0=ld4(&sA[k][r0]), x1=ld4(&sA[k][r0+4]);
            float4 y0=ld4(&sW[k][c0]), y1=ld4(&sW[k][c0+4]);
            float xs[8]={x0.x,x0.y,x0.z,x0.w,x1.x,x1.y,x1.z,x1.w};
            float ys[8]={y0.x,y0.y,y0.z,y0.w,y1.x,y1.y,y1.z,y1.w};
#pragma unroll
            for (int i=0;i<8;i++)
#pragma unroll
                for (int j=0;j<8;j++)
                    acc[i][j] = fmaf(xs[i], ys[j], acc[i][j]);
        }
    }
#pragma unroll
    for (int i=0;i<8;i++){
        float* cr = Cb + (r0+i)*ldc;
#pragma unroll
        for (int j=0;j<8;j++){
            int c = c0+j;
            if (c < nvalid) cr[c] = acc[i][j];
        }
    }
}

// ---------------- precompute GEMM: C[M,512]=A[M,512]@W[512,512]^T + b ------
// grid.x = 8 (N tiles), grid.y = M/64; outsel: 0->g_k, 1->g_v, 2->g_s[0]
__global__ __launch_bounds__(64) void k_gemm_pre(
    const float* __restrict__ A, const float* __restrict__ W,
    const float* __restrict__ bias, int outsel, int act)
{
    __shared__ float sA[16][64];
    __shared__ float sW[16][64];
    float acc[8][8];
#pragma unroll
    for (int i=0;i<8;i++)
#pragma unroll
        for (int j=0;j<8;j++) acc[i][j]=0.f;

    const int t  = threadIdx.x;
    const int r0 = (t>>3)<<3;
    const int c0 = (t&7)<<3;
    const int m0 = blockIdx.y*64;
    const int n0 = blockIdx.x*64;
    const float* Arow = A + (size_t)(m0+t)*512;
    const float* Wrow = W + (size_t)(n0+t)*512;

    for (int kc=0; kc<512; kc+=16){
        float4 a0=ld4(Arow+kc), a1=ld4(Arow+kc+4), a2=ld4(Arow+kc+8), a3=ld4(Arow+kc+12);
        float4 w0=ld4(Wrow+kc), w1=ld4(Wrow+kc+4), w2=ld4(Wrow+kc+8), w3=ld4(Wrow+kc+12);
        __syncthreads();
        sA[ 0][t]=a0.x; sA[ 1][t]=a0.y; sA[ 2][t]=a0.z; sA[ 3][t]=a0.w;
        sA[ 4][t]=a1.x; sA[ 5][t]=a1.y; sA[ 6][t]=a1.z; sA[ 7][t]=a1.w;
        sA[ 8][t]=a2.x; sA[ 9][t]=a2.y; sA[10][t]=a2.z; sA[11][t]=a2.w;
        sA[12][t]=a3.x; sA[13][t]=a3.y; sA[14][t]=a3.z; sA[15][t]=a3.w;
        sW[ 0][t]=w0.x; sW[ 1][t]=w0.y; sW[ 2][t]=w0.z; sW[ 3][t]=w0.w;
        sW[ 4][t]=w1.x; sW[ 5][t]=w1.y; sW[ 6][t]=w1.z; sW[ 7][t]=w1.w;
        sW[ 8][t]=w2.x; sW[ 9][t]=w2.y; sW[10][t]=w2.z; sW[11][t]=w2.w;
        sW[12][t]=w3.x; sW[13][t]=w3.y; sW[14][t]=w3.z; sW[15][t]=w3.w;
        __syncthreads();
#pragma unroll
        for (int k=0;k<16;k++){
            float4 x0=ld4(&sA[k][r0]), x1=ld4(&sA[k][r0+4]);
            float4 y0=ld4(&sW[k][c0]), y1=ld4(&sW[k][c0+4]);
            float xs[8]={x0.x,x0.y,x0.z,x0.w,x1.x,x1.y,x1.z,x1.w};
            float ys[8]={y0.x,y0.y,y0.z,y0.w,y1.x,y1.y,y1.z,y1.w};
#pragma unroll
            for (int i=0;i<8;i++)
#pragma unroll
                for (int j=0;j<8;j++)
                    acc[i][j] = fmaf(xs[i], ys[j], acc[i][j]);
        }
    }
    float* C = (outsel==0) ? g_k : (outsel==1) ? g_v : g_s[0];
#pragma unroll
    for (int i=0;i<8;i++){
        float* cr = C + (size_t)(m0+r0+i)*512 + n0;
#pragma unroll
        for (int j=0;j<8;j++){
            float v = acc[i][j] + bias[n0+c0+j];
            if (act) v = tanhf(v);
            cr[c0+j] = v;
        }
    }
}

// ---------------- step kernels ----------------
// q GEMM: q[64,512] = s @ wq^T ; grid (8 ntiles, 8 kparts)
__global__ __launch_bounds__(64) void k_qgemm(const float* __restrict__ wq, int cur)
{
    int n0 = blockIdx.x*64;
    int kp = blockIdx.y;
    int k0 = kp*64;
    gemm64_kc64(&g_s[cur][k0], DD, wq + (size_t)n0*DD + k0, DD,
                &g_qpart[kp][n0], DD, 64);
}

// attention: per-batch block; sums q parts + bias; scores/softmax/r
__global__ __launch_bounds__(256) void k_attn(const float* __restrict__ bq,
                                              const int* __restrict__ mask)
{
    __shared__ float sq[DD];
    __shared__ float sal[NN];
    const int b = blockIdx.x, tid = threadIdx.x;

    for (int d=tid; d<DD; d+=256){
        float x = bq[d];
#pragma unroll
        for (int p=0;p<8;p++) x += g_qpart[p][b*DD+d];
        sq[d] = x;
    }
    __syncthreads();

    const int warp = tid>>5, lane = tid&31;
    for (int n=warp; n<NN; n+=8){
        const float* kp = &g_k[((size_t)b*NN+n)*DD];
        float acc = 0.f;
        for (int d=lane; d<DD; d+=32) acc = fmaf(sq[d], kp[d], acc);
#pragma unroll
        for (int o=16;o>0;o>>=1) acc += __shfl_down_sync(0xffffffffu, acc, o);
        if (lane==0) sal[n] = (mask[b*NN+n]==0) ? -1e9f : acc;
    }
    __syncthreads();

    if (warp==0){
        float x0 = sal[lane], x1 = sal[lane+32];
        float m = fmaxf(x0,x1);
#pragma unroll
        for (int o=16;o>0;o>>=1) m = fmaxf(m, __shfl_xor_sync(0xffffffffu, m, o));
        float e0 = expf(x0-m), e1 = expf(x1-m);
        float s = e0+e1;
#pragma unroll
        for (int o=16;o>0;o>>=1) s += __shfl_xor_sync(0xffffffffu, s, o);
        float inv = 1.f/s;
        sal[lane] = e0*inv; sal[lane+32] = e1*inv;
    }
    __syncthreads();

    for (int d=tid; d<DD; d+=256){
        float a0=0.f,a1=0.f,a2=0.f,a3=0.f;
#pragma unroll 4
        for (int n=0;n<NN;n+=4){
            a0 = fmaf(sal[n+0], g_v[((size_t)b*NN+n+0)*DD+d], a0);
            a1 = fmaf(sal[n+1], g_v[((size_t)b*NN+n+1)*DD+d], a1);
            a2 = fmaf(sal[n+2], g_v[((size_t)b*NN+n+2)*DD+d], a2);
            a3 = fmaf(sal[n+3], g_v[((size_t)b*NN+n+3)*DD+d], a3);
        }
        g_r[b*DD+d] = (a0+a1)+(a2+a3);
    }
}

// gates: grid (24 ntiles over 1536, 24 = 16 gi parts + 8 gh parts)
__global__ __launch_bounds__(64) void k_gates(const float* __restrict__ w_ih,
                                              const float* __restrict__ w_hh,
                                              const float* __restrict__ grep, int cur)
{
    int n0 = blockIdx.x*64;
    int y  = blockIdx.y;
    if (y < 16){
        int k0 = y*64;
        const float* Ab = (k0 < 512) ? &g_r[k0] : (grep + (k0-512));
        gemm64_kc64(Ab, DD, w_ih + (size_t)n0*1024 + k0, 1024,
                    &g_gipart[y][n0], 1536, 64);
    } else {
        int p = y-16, k0 = p*64;
        gemm64_kc64(&g_s[cur][k0], DD, w_hh + (size_t)n0*512 + k0, 512,
                    &g_ghpart[p][n0], 1536, 64);
    }
}

// combine: GRU gates -> s_new, plus loc -> (i,j). One block per batch, 512 thr.
__global__ __launch_bounds__(512) void k_combine(
    const float* __restrict__ b_ih, const float* __restrict__ b_hh,
    const float* __restrict__ grep, const float* __restrict__ w_loc,
    const float* __restrict__ b_loc, int cur)
{
    const int b = blockIdx.x, j = threadIdx.x;
    const int base = b*1536;

    float ir=b_ih[j], iz=b_ih[512+j], inn=b_ih[1024+j];
#pragma unroll
    for (int p=0;p<16;p++){
        const float* gp = &g_gipart[p][base];
        ir += gp[j]; iz += gp[512+j]; inn += gp[1024+j];
    }
    float hr=b_hh[j], hz=b_hh[512+j], hn=b_hh[1024+j];
#pragma unroll
    for (int p=0;p<8;p++){
        const float* gp = &g_ghpart[p][base];
        hr += gp[j]; hz += gp[512+j]; hn += gp[1024+j];
    }
    float rg = 1.f/(1.f+expf(-(ir+hr)));
    float zg = 1.f/(1.f+expf(-(iz+hz)));
    float ng = tanhf(inn + rg*hn);
    float so = g_s[cur][b*DD+j];
    float sn = (1.f-zg)*ng + zg*so;
    g_s[1-cur][b*DD+j] = sn;

    // loc partials (only components 0 and 1 are used)
    float rj = g_r[b*DD+j], gj = grep[b*DD+j];
    float p0 = sn*w_loc[j]      + rj*w_loc[512+j]      + gj*w_loc[1024+j];
    float p1 = sn*w_loc[1536+j] + rj*w_loc[1536+512+j] + gj*w_loc[1536+1024+j];

    __shared__ float red[2][16];
    const int warp = j>>5, lane = j&31;
#pragma unroll
    for (int o=16;o>0;o>>=1){
        p0 += __shfl_xor_sync(0xffffffffu, p0, o);
        p1 += __shfl_xor_sync(0xffffffffu, p1, o);
    }
    if (lane==0){ red[0][warp]=p0; red[1][warp]=p1; }
    __syncthreads();
    if (j==0){
        float l0=b_loc[0], l1=b_loc[1];
#pragma unroll
        for (int w=0;w<16;w++){ l0+=red[0][w]; l1+=red[1][w]; }
        float cx = tanhf(l0), cy = tanhf(l1);
        int jx = (int)rintf(0.5f*(cx+1.f)*(float)(WW-1));
        int iy = (int)rintf(0.5f*(cy+1.f)*(float)(HH-1));
        jx = min(WW-1, max(0, jx));
        iy = min(HH-1, max(0, iy));
        g_ij[b*2]   = iy;
        g_ij[b*2+1] = jx;
    }
}

// patch GEMM: patch[64,400] = [s_new, r] @ w_write^T ; grid (7 ntiles, 16 kparts)
__global__ __launch_bounds__(64) void k_pgemm(const float* __restrict__ w_write, int nxt)
{
    int n0 = blockIdx.x*64;
    int p  = blockIdx.y;
    int k0 = p*64;
    const float* Ab = (k0 < 512) ? &g_s[nxt][k0] : &g_r[k0-512];
    int nvalid = min(64, 400 - n0);
    gemm64_kc64(Ab, DD, w_write + (size_t)n0*1024 + k0, 1024,
                &g_ppart[p][n0], 448, nvalid);
}

// scatter: sum patch parts + bias, add into d_out with clipping
__global__ __launch_bounds__(128) void k_scatter(const float* __restrict__ b_write,
                                                 float* __restrict__ out)
{
    const int b = blockIdx.x, tid = threadIdx.x;
    const int iy = g_ij[b*2], jx = g_ij[b*2+1];
    for (int c=tid; c<400; c+=128){
        float v = b_write[c];
#pragma unroll
        for (int p=0;p<16;p++) v += g_ppart[p][b*448+c];
        int ch = c/25, rem = c%25, ki = rem/5, kj = rem%5;
        int row = iy + ki - 2, col = jx + kj - 2;
        if (row >= 0 && row < HH && col >= 0 && col < WW){
            size_t o = (((size_t)b*CCH + ch)*HH + row)*WW + col;
            out[o] += v;
        }
    }
}

// zero output
__global__ void k_zero(float4* __restrict__ p, int n4)
{
    for (int i = blockIdx.x*blockDim.x + threadIdx.x; i < n4; i += gridDim.x*blockDim.x)
        p[i] = make_float4(0.f,0.f,0.f,0.f);
}

// ---------------- launch ----------------
extern "C" void kernel_launch(void* const* d_in, const int* in_sizes, int n_in,
                              void* d_out, int out_size)
{
    const float* token_reps = (const float*)d_in[0];
    const float* global_rep = (const float*)d_in[1];
    const int*   mask       = (const int*)  d_in[2];
    const float* w_init     = (const float*)d_in[3];
    const float* b_init     = (const float*)d_in[4];
    const float* wq         = (const float*)d_in[5];
    const float* bq         = (const float*)d_in[6];
    const float* wk         = (const float*)d_in[7];
    const float* bk         = (const float*)d_in[8];
    const float* wv         = (const float*)d_in[9];
    const float* bv         = (const float*)d_in[10];
    const float* w_ih       = (const float*)d_in[11];
    const float* b_ih       = (const float*)d_in[12];
    const float* w_hh       = (const float*)d_in[13];
    const float* b_hh       = (const float*)d_in[14];
    const float* w_write    = (const float*)d_in[15];
    const float* b_write    = (const float*)d_in[16];
    const float* w_loc      = (const float*)d_in[17];
    const float* b_loc      = (const float*)d_in[18];
    float* out = (float*)d_out;

    k_zero<<<2048,256>>>((float4*)out, out_size/4);

    // precompute k_tok, v_tok, s0
    k_gemm_pre<<<dim3(8,64),64>>>(token_reps, wk, bk, 0, 0);
    k_gemm_pre<<<dim3(8,64),64>>>(token_reps, wv, bv, 1, 0);
    k_gemm_pre<<<dim3(8,1), 64>>>(global_rep, w_init, b_init, 2, 1);

    for (int t=0; t<TSTEPS; t++){
        int cur = t & 1;
        k_qgemm  <<<dim3(8,8),  64>>>(wq, cur);
        k_attn   <<<64, 256>>>(bq, mask);
        k_gates  <<<dim3(24,24),64>>>(w_ih, w_hh, global_rep, cur);
        k_combine<<<64, 512>>>(b_ih, b_hh, global_rep, w_loc, b_loc, cur);
        k_pgemm  <<<dim3(7,16), 64>>>(w_write, 1-cur);
        k_scatter<<<64, 128>>>(b_write, out);
    }
}

// round 2
// speedup vs baseline: 1.6772x; 1.6772x over previous
#include <cuda_runtime.h>

#define GRID 148
#define NT   256

typedef unsigned long long ull;

// ---------------- device scratch ----------------
__device__ float g_k[64*64*512];
__device__ float g_v[64*64*512];
__device__ float g_s[2][64*512];
__device__ float g_r[64*512];
__device__ float g_gig[64*1536];
__device__ float g_qp[8][64*512];
__device__ float g_gip[8][64*1536];
__device__ float g_ghp[8][64*1536];
__device__ float g_pp[16][64*512];
__device__ int   g_ij[64*2];
__device__ unsigned g_barc;
__device__ unsigned g_barg;

__device__ __forceinline__ float4 ld4(const float* p){ return *reinterpret_cast<const float4*>(p); }

__device__ __forceinline__ ull pack2(float x){
    ull d; unsigned u = __float_as_uint(x);
    asm("mov.b64 %0, {%1, %1};" : "=l"(d) : "r"(u));
    return d;
}
__device__ __forceinline__ ull fma2(ull a, ull b, ull c){
    ull d;
    asm("fma.rn.f32x2 %0, %1, %2, %3;" : "=l"(d) : "l"(a), "l"(b), "l"(c));
    return d;
}

// ---------------- grid barrier ----------------
__device__ __forceinline__ void gsync(){
    __syncthreads();
    if (threadIdx.x == 0){
        volatile unsigned* vg = &g_barg;
        unsigned gen = *vg;
        __threadfence();
        if (atomicAdd(&g_barc, 1u) == GRID-1u){
            atomicExch(&g_barc, 0u);
            __threadfence();
            atomicAdd(&g_barg, 1u);
        } else {
            while (*vg == gen) __nanosleep(64);
            __threadfence();
        }
    }
    __syncthreads();
}

// ---------------- 64 x <=128 tile GEMM, K = kchunks*64, f32x2 core ----------
// C[m, col] = sum_k A[m, k] * W[col, k]; A rows always 64.
// epi: 0 raw, 1 +bias, 2 tanh(x+bias)
__device__ void gemm_tile(const float* __restrict__ A, int lda,
                          const float* __restrict__ W, int ldw,
                          int kchunks, int wrows,
                          float* __restrict__ C, int ldc,
                          const float* __restrict__ bias, int epi,
                          float* sA, float* sW)
{
    const int tid = threadIdx.x;
    const int ty = tid >> 4;          // 0..15 -> rows ty*4..+3
    const int tx = tid & 15;          // col pairs 32*j + 2*tx
    ull acc[16];
#pragma unroll
    for (int i=0;i<16;i++) acc[i] = 0ull;

    const int am  = tid & 63,  akq = tid >> 6;   // A loader
    const int wn  = tid & 127, wkq = tid >> 7;   // W loader
    const bool wok = wn < wrows;

    for (int c=0;c<kchunks;c++){
        const int kc = c*64;
        const float* ap = A + (size_t)am*lda + kc + akq*16;
#pragma unroll
        for (int u=0;u<4;u++){
            float4 v = ld4(ap + u*4);
            int k = akq*16 + u*4;
            sA[(k+0)*64+am]=v.x; sA[(k+1)*64+am]=v.y;
            sA[(k+2)*64+am]=v.z; sA[(k+3)*64+am]=v.w;
        }
        const float* wp = W + (size_t)wn*ldw + kc + wkq*32;
#pragma unroll
        for (int u=0;u<8;u++){
            float4 v = wok ? ld4(wp + u*4) : make_float4(0.f,0.f,0.f,0.f);
            int k = wkq*32 + u*4;
            sW[(k+0)*128+wn]=v.x; sW[(k+1)*128+wn]=v.y;
            sW[(k+2)*128+wn]=v.z; sW[(k+3)*128+wn]=v.w;
        }
        __syncthreads();
#pragma unroll 8
        for (int k=0;k<64;k++){
            float4 a = ld4(&sA[k*64 + ty*4]);
            ull x0=pack2(a.x), x1=pack2(a.y), x2=pack2(a.z), x3=pack2(a.w);
            const float* wr = &sW[k*128 + tx*2];
            ull w0=*(const ull*)(wr);
            ull w1=*(const ull*)(wr+32);
            ull w2=*(const ull*)(wr+64);
            ull w3=*(const ull*)(wr+96);
            acc[ 0]=fma2(x0,w0,acc[ 0]); acc[ 1]=fma2(x0,w1,acc[ 1]);
            acc[ 2]=fma2(x0,w2,acc[ 2]); acc[ 3]=fma2(x0,w3,acc[ 3]);
            acc[ 4]=fma2(x1,w0,acc[ 4]); acc[ 5]=fma2(x1,w1,acc[ 5]);
            acc[ 6]=fma2(x1,w2,acc[ 6]); acc[ 7]=fma2(x1,w3,acc[ 7]);
            acc[ 8]=fma2(x2,w0,acc[ 8]); acc[ 9]=fma2(x2,w1,acc[ 9]);
            acc[10]=fma2(x2,w2,acc[10]); acc[11]=fma2(x2,w3,acc[11]);
            acc[12]=fma2(x3,w0,acc[12]); acc[13]=fma2(x3,w1,acc[13]);
            acc[14]=fma2(x3,w2,acc[14]); acc[15]=fma2(x3,w3,acc[15]);
        }
        __syncthreads();
    }
#pragma unroll
    for (int i=0;i<4;i++){
        const int m = ty*4 + i;
#pragma unroll
        for (int j=0;j<4;j++){
            const int col = tx*2 + 32*j;
            if (col < wrows){
                ull a = acc[i*4+j];
                float2 v;
                v.x = __uint_as_float((unsigned)(a & 0xffffffffull));
                v.y = __uint_as_float((unsigned)(a >> 32));
                if (epi == 1){ v.x += bias[col]; v.y += bias[col+1]; }
                else if (epi == 2){ v.x = tanhf(v.x + bias[col]); v.y = tanhf(v.y + bias[col+1]); }
                *reinterpret_cast<float2*>(C + (size_t)m*ldc + col) = v;
            }
        }
    }
}

// ---------------- attention task (one batch per CTA) ----------------
__device__ void attn_task(int b, const float* __restrict__ bq,
                          const int* __restrict__ mask, float* sm)
{
    float* sq  = sm;        // 512
    float* sal = sm + 512;  // 64
    const int tid = threadIdx.x;

    for (int d=tid; d<512; d+=NT){
        float x = bq[d];
#pragma unroll
        for (int p=0;p<8;p++) x += g_qp[p][b*512+d];
        sq[d] = x;
    }
    __syncthreads();

    const int warp = tid>>5, lane = tid&31;
    for (int n=warp; n<64; n+=8){
        const float* kp = &g_k[((size_t)b*64+n)*512];
        float acc = 0.f;
#pragma unroll
        for (int c=0;c<4;c++){
            float4 kv = ld4(kp + c*128 + lane*4);
            float4 qv = ld4(sq + c*128 + lane*4);
            acc = fmaf(kv.x,qv.x,acc); acc = fmaf(kv.y,qv.y,acc);
            acc = fmaf(kv.z,qv.z,acc); acc = fmaf(kv.w,qv.w,acc);
        }
#pragma unroll
        for (int o=16;o>0;o>>=1) acc += __shfl_down_sync(0xffffffffu, acc, o);
        if (lane==0) sal[n] = (mask[b*64+n]==0) ? -1e9f : acc;
    }
    __syncthreads();

    if (warp==0){
        float x0 = sal[lane], x1 = sal[lane+32];
        float m = fmaxf(x0,x1);
#pragma unroll
        for (int o=16;o>0;o>>=1) m = fmaxf(m, __shfl_xor_sync(0xffffffffu, m, o));
        float e0 = expf(x0-m), e1 = expf(x1-m);
        float s = e0+e1;
#pragma unroll
        for (int o=16;o>0;o>>=1) s += __shfl_xor_sync(0xffffffffu, s, o);
        float inv = 1.f/s;
        sal[lane] = e0*inv; sal[lane+32] = e1*inv;
    }
    __syncthreads();

    {
        const int d = tid*2;
        float a0=0.f, a1=0.f;
        const float* vb = &g_v[(size_t)b*64*512 + d];
#pragma unroll 4
        for (int n=0;n<64;n++){
            float al = sal[n];
            float2 vv = *reinterpret_cast<const float2*>(vb + (size_t)n*512);
            a0 = fmaf(al, vv.x, a0);
            a1 = fmaf(al, vv.y, a1);
        }
        g_r[b*512+d]   = a0;
        g_r[b*512+d+1] = a1;
    }
}

// ---------------- scatter task (one batch per CTA) ----------------
__device__ void scatter_task(int b, const float* __restrict__ b_write,
                             float* __restrict__ out)
{
    const int tid = threadIdx.x;
    const int iy = g_ij[b*2], jx = g_ij[b*2+1];
    for (int c=tid; c<400; c+=NT){
        float v = b_write[c];
#pragma unroll
        for (int p=0;p<16;p++) v += g_pp[p][b*512+c];
        int ch = c/25, rem = c - ch*25;
        int ki = rem/5, kj = rem - ki*5;
        int row = iy + ki - 2, col = jx + kj - 2;
        if ((unsigned)row < 128u && (unsigned)col < 128u){
            size_t o = (((size_t)b*16 + ch)*128 + row)*128 + col;
            out[o] += v;
        }
    }
}

// ---------------- combine task (one batch per CTA) ----------------
__device__ void combine_task(int b, int cur,
                             const float* __restrict__ grep,
                             const float* __restrict__ b_hh,
                             const float* __restrict__ w_loc,
                             const float* __restrict__ b_loc,
                             float* sm)
{
    const int tid = threadIdx.x;
    float p0 = 0.f, p1 = 0.f;

#pragma unroll
    for (int h=0; h<2; h++){
        const int jj = tid + h*256;
        const int base = b*1536;
        float ir = g_gig[base+jj], iz = g_gig[base+512+jj], inn = g_gig[base+1024+jj];
#pragma unroll
        for (int p=0;p<8;p++){
            const float* gp = &g_gip[p][base];
            ir += gp[jj]; iz += gp[512+jj]; inn += gp[1024+jj];
        }
        float hr = b_hh[jj], hz = b_hh[512+jj], hn = b_hh[1024+jj];
#pragma unroll
        for (int p=0;p<8;p++){
            const float* gp = &g_ghp[p][base];
            hr += gp[jj]; hz += gp[512+jj]; hn += gp[1024+jj];
        }
        float rg = 1.f/(1.f+expf(-(ir+hr)));
        float zg = 1.f/(1.f+expf(-(iz+hz)));
        float ng = tanhf(inn + rg*hn);
        float so = g_s[cur][b*512+jj];
        float sn = (1.f-zg)*ng + zg*so;
        g_s[cur^1][b*512+jj] = sn;

        float rr = g_r[b*512+jj], gg = grep[b*512+jj];
        p0 += sn*w_loc[jj]      + rr*w_loc[512+jj]  + gg*w_loc[1024+jj];
        p1 += sn*w_loc[1536+jj] + rr*w_loc[2048+jj] + gg*w_loc[2560+jj];
    }

    const int warp = tid>>5, lane = tid&31;
#pragma unroll
    for (int o=16;o>0;o>>=1){
        p0 += __shfl_xor_sync(0xffffffffu, p0, o);
        p1 += __shfl_xor_sync(0xffffffffu, p1, o);
    }
    if (lane==0){ sm[warp] = p0; sm[8+warp] = p1; }
    __syncthreads();
    if (tid==0){
        float l0 = b_loc[0], l1 = b_loc[1];
#pragma unroll
        for (int w=0;w<8;w++){ l0 += sm[w]; l1 += sm[8+w]; }
        float cx = tanhf(l0), cy = tanhf(l1);
        int jx = (int)rintf(0.5f*(cx+1.f)*127.f);
        int iy = (int)rintf(0.5f*(cy+1.f)*127.f);
        jx = min(127, max(0, jx));
        iy = min(127, max(0, iy));
        g_ij[b*2]   = iy;
        g_ij[b*2+1] = jx;
    }
}

// ---------------- the persistent kernel ----------------
__global__ void __launch_bounds__(NT, 1) painter(
    const float* __restrict__ tok,   const float* __restrict__ grep,
    const int*   __restrict__ mask,
    const float* __restrict__ w_init, const float* __restrict__ b_init,
    const float* __restrict__ wq,     const float* __restrict__ bq,
    const float* __restrict__ wk,     const float* __restrict__ bk,
    const float* __restrict__ wv,     const float* __restrict__ bv,
    const float* __restrict__ w_ih,   const float* __restrict__ b_ih,
    const float* __restrict__ w_hh,   const float* __restrict__ b_hh,
    const float* __restrict__ w_write,const float* __restrict__ b_write,
    const float* __restrict__ w_loc,  const float* __restrict__ b_loc,
    float* __restrict__ out, int out_n)
{
    __shared__ float sA[64*64];
    __shared__ float sW[64*128];
    const int bid = blockIdx.x, tid = threadIdx.x;

    // ---- P0: k_tok, v_tok, s0, gi_g, zero canvas ----
    for (int task = bid; task < 592; task += GRID){
        if (task < 512){
            int mat = task >> 8, rem = task & 255;
            int m0 = (rem >> 2)*64, n0 = (rem & 3)*128;
            const float* W    = mat ? wv : wk;
            const float* bias = mat ? bv : bk;
            float* dst        = mat ? g_v : g_k;
            gemm_tile(tok + (size_t)m0*512, 512, W + (size_t)n0*512, 512, 8, 128,
                      dst + (size_t)m0*512 + n0, 512, bias + n0, 1, sA, sW);
        } else if (task < 516){
            int n0 = (task-512)*128;
            gemm_tile(grep, 512, w_init + (size_t)n0*512, 512, 8, 128,
                      g_s[0] + n0, 512, b_init + n0, 2, sA, sW);
        } else if (task < 528){
            int n0 = (task-516)*128;
            gemm_tile(grep, 512, w_ih + (size_t)n0*1024 + 512, 1024, 8, 128,
                      g_gig + n0, 1536, b_ih + n0, 1, sA, sW);
        } else {
            int z = task - 528;
            int per4 = (out_n/64)/4;      // 65536 float4
            float4* p = reinterpret_cast<float4*>(out) + (size_t)z*per4;
            for (int i=tid; i<per4; i+=NT) p[i] = make_float4(0.f,0.f,0.f,0.f);
        }
    }
    gsync();

    for (int t=0; t<=32; t++){
        const int cur = t & 1;
        const float* scur = g_s[cur];

        // phase 1: q(32, t<32) + gh(96, t<32) + patch(64, t>0)
        for (int task=bid; task<192; task+=GRID){
            if (task < 32){
                if (t < 32){
                    int n0 = (task & 3)*128, kp = task >> 2;
                    gemm_tile(scur + kp*64, 512, wq + (size_t)n0*512 + kp*64, 512, 1, 128,
                              g_qp[kp] + n0, 512, 0, 0, sA, sW);
                }
            } else if (task < 128){
                if (t < 32){
                    int id = task-32;
                    int n0 = (id % 12)*128, kp = id/12;
                    gemm_tile(scur + kp*64, 512, w_hh + (size_t)n0*512 + kp*64, 512, 1, 128,
                              g_ghp[kp] + n0, 1536, 0, 0, sA, sW);
                }
            } else {
                if (t > 0){
                    int id = task-128;
                    int n0 = (id & 3)*128, kp = id >> 2;
                    const float* Ab = (kp < 8) ? (scur + kp*64) : (g_r + (kp-8)*64);
                    int wr = (n0 == 384) ? 16 : 128;
                    gemm_tile(Ab, 512, w_write + (size_t)n0*1024 + kp*64, 1024, 1, wr,
                              g_pp[kp] + n0, 512, 0, 0, sA, sW);
                }
            }
        }
        gsync();

        // phase 2: attn(64, t<32) + scatter(64, t>0)
        for (int task=bid; task<128; task+=GRID){
            if (task < 64){
                if (t < 32) attn_task(task, bq, mask, sA);
            } else {
                if (t > 0) scatter_task(task-64, b_write, out);
            }
        }
        gsync();

        if (t < 32){
            // phase 3: gi_r (96 tasks)
            for (int task=bid; task<96; task+=GRID){
                int n0 = (task % 12)*128, kp = task/12;
                gemm_tile(g_r + kp*64, 512, w_ih + (size_t)n0*1024 + kp*64, 1024, 1, 128,
                          g_gip[kp] + n0, 1536, 0, 0, sA, sW);
            }
            gsync();

            // phase 4: combine (64 tasks)
            for (int task=bid; task<64; task+=GRID)
                combine_task(task, cur, grep, b_hh, w_loc, b_loc, sA);
            gsync();
        }
    }
}

// ---------------- launch ----------------
extern "C" void kernel_launch(void* const* d_in, const int* in_sizes, int n_in,
                              void* d_out, int out_size)
{
    const float* token_reps = (const float*)d_in[0];
    const float* global_rep = (const float*)d_in[1];
    const int*   mask       = (const int*)  d_in[2];
    const float* w_init     = (const float*)d_in[3];
    const float* b_init     = (const float*)d_in[4];
    const float* wq         = (const float*)d_in[5];
    const float* bq         = (const float*)d_in[6];
    const float* wk         = (const float*)d_in[7];
    const float* bk         = (const float*)d_in[8];
    const float* wv         = (const float*)d_in[9];
    const float* bv         = (const float*)d_in[10];
    const float* w_ih       = (const float*)d_in[11];
    const float* b_ih       = (const float*)d_in[12];
    const float* w_hh       = (const float*)d_in[13];
    const float* b_hh       = (const float*)d_in[14];
    const float* w_write    = (const float*)d_in[15];
    const float* b_write    = (const float*)d_in[16];
    const float* w_loc      = (const float*)d_in[17];
    const float* b_loc      = (const float*)d_in[18];

    painter<<<GRID, NT>>>(token_reps, global_rep, mask,
                          w_init, b_init, wq, bq, wk, bk, wv, bv,
                          w_ih, b_ih, w_hh, b_hh, w_write, b_write,
                          w_loc, b_loc, (float*)d_out, out_size);
}

// round 3
// speedup vs baseline: 2.1987x; 1.3109x over previous
#include <cuda_runtime.h>

#define GRID 148
#define NT   512
#define KC   16

typedef unsigned long long ull;

// ---------------- device scratch ----------------
__device__ float g_k [64*64*512];    // k_tok
__device__ float g_v [64*64*512];    // v_tok
__device__ float g_kp[64*64*512];    // K' = k @ wq
__device__ float g_vp[64*64*1536];   // V' = v @ w_ih[:, :512]^T
__device__ float g_c0[64*64];        // bq . k (masked)
__device__ float g_s[2][64*512];
__device__ float g_r[2][64*512];
__device__ float g_gig[64*1536];     // grep part of gi (+ b_ih)
__device__ float g_gir[64*1536];     // r part of gi (from attn task)
__device__ float g_ghp[8][64*1536];  // gh split-K parts
__device__ float g_pp[16][64*512];   // patch split-K parts
__device__ int   g_ij[2][64*2];
__device__ unsigned g_barc, g_barg;

__device__ __forceinline__ float4 ld4(const float* p){ return *reinterpret_cast<const float4*>(p); }

__device__ __forceinline__ ull pack2(float x){
    ull d; unsigned u = __float_as_uint(x);
    asm("mov.b64 %0, {%1, %1};" : "=l"(d) : "r"(u));
    return d;
}
__device__ __forceinline__ ull fma2(ull a, ull b, ull c){
    ull d;
    asm("fma.rn.f32x2 %0, %1, %2, %3;" : "=l"(d) : "l"(a), "l"(b), "l"(c));
    return d;
}
__device__ __forceinline__ float lo32(ull a){ return __uint_as_float((unsigned)a); }
__device__ __forceinline__ float hi32(ull a){ return __uint_as_float((unsigned)(a>>32)); }

// ---------------- grid barrier ----------------
__device__ __forceinline__ void gsync(){
    __syncthreads();
    if (threadIdx.x == 0){
        volatile unsigned* vg = &g_barg;
        unsigned gen = *vg;
        __threadfence();
        if (atomicAdd(&g_barc, 1u) == GRID-1u){
            atomicExch(&g_barc, 0u);
            __threadfence();
            atomicAdd(&g_barg, 1u);
        } else {
            while (*vg == gen) __nanosleep(32);
            __threadfence();
        }
    }
    __syncthreads();
}

// ---------------- 64 x <=256 tile GEMM, double-buffered, f32x2 ----------
// C[m,col] = sum_k A[m,k]*Wv[col,k].  wkm=0: W row-major [col, ldw].
// wkm=1: W k-major [k, ldw] (W pre-offset to col tile).
// epi: 0 raw, 1 +bias, 2 tanh(+bias)
__device__ void gemm_t(const float* __restrict__ A, int lda,
                       const float* __restrict__ W, int ldw, int wkm,
                       int nchunks, int wcols,
                       float* __restrict__ C, int ldc,
                       const float* __restrict__ bias, int epi,
                       float* __restrict__ sA, float* __restrict__ sW)
{
    const int tid = threadIdx.x;
    const int ty = tid >> 6;          // 0..7  rows ty*8..+7
    const int tx = tid & 63;          // cols tx + 64j

    ull acc[4][4];
#pragma unroll
    for (int p=0;p<4;p++)
#pragma unroll
        for (int j=0;j<4;j++) acc[p][j]=0ull;

    // loader indices
    const int  am  = tid & 63;
    const int  akq = (tid>>6) & 3;
    const bool aok = tid < 256;
    const int  wn  = tid & 255;
    const int  kq0 = (tid>>8)*2;
    const int  kk  = tid >> 6;
    const int  col4= (tid & 63)*4;
    const bool wok = wn < wcols;
    const float4 f40 = make_float4(0.f,0.f,0.f,0.f);

    float4 ra=f40, rw0=f40, rw1=f40;

    // load chunk 0
    if (aok) ra = ld4(A + (size_t)am*lda + akq*4);
    if (wkm){ rw0 = ld4(W + (size_t)kk*ldw + col4); rw1 = ld4(W + (size_t)(kk+8)*ldw + col4); }
    else {
        rw0 = wok ? ld4(W + (size_t)wn*ldw + kq0*4)     : f40;
        rw1 = wok ? ld4(W + (size_t)wn*ldw + kq0*4 + 4) : f40;
    }
    __syncthreads();   // smem may still be read by previous task
    // store chunk 0 -> buf 0
    {
        if (aok){
            float* d = sA;
            d[(akq*4+0)*64+am]=ra.x; d[(akq*4+1)*64+am]=ra.y;
            d[(akq*4+2)*64+am]=ra.z; d[(akq*4+3)*64+am]=ra.w;
        }
        if (wkm){
            *reinterpret_cast<float4*>(sW + kk*256 + col4)    = rw0;
            *reinterpret_cast<float4*>(sW + (kk+8)*256 + col4)= rw1;
        } else {
            float* d = sW;
            d[(kq0*4+0)*256+wn]=rw0.x; d[(kq0*4+1)*256+wn]=rw0.y;
            d[(kq0*4+2)*256+wn]=rw0.z; d[(kq0*4+3)*256+wn]=rw0.w;
            d[(kq0*4+4)*256+wn]=rw1.x; d[(kq0*4+5)*256+wn]=rw1.y;
            d[(kq0*4+6)*256+wn]=rw1.z; d[(kq0*4+7)*256+wn]=rw1.w;
        }
    }
    __syncthreads();

    for (int c=0; c<nchunks; c++){
        const bool more = (c+1) < nchunks;
        const int kc = (c+1)*KC;
        if (more){
            if (aok) ra = ld4(A + (size_t)am*lda + kc + akq*4);
            if (wkm){ rw0 = ld4(W + (size_t)(kc+kk)*ldw + col4); rw1 = ld4(W + (size_t)(kc+kk+8)*ldw + col4); }
            else {
                rw0 = wok ? ld4(W + (size_t)wn*ldw + kc + kq0*4)     : f40;
                rw1 = wok ? ld4(W + (size_t)wn*ldw + kc + kq0*4 + 4) : f40;
            }
        }
        const float* cA = sA + (c&1)*KC*64;
        const float* cW = sW + (c&1)*KC*256;
#pragma unroll
        for (int k=0;k<KC;k++){
            ulonglong2 a01 = *reinterpret_cast<const ulonglong2*>(cA + k*64 + ty*8);
            ulonglong2 a23 = *reinterpret_cast<const ulonglong2*>(cA + k*64 + ty*8 + 4);
            ull ap0=a01.x, ap1=a01.y, ap2=a23.x, ap3=a23.y;
            const float* wr = cW + k*256 + tx;
            ull w0=pack2(wr[0]), w1=pack2(wr[64]), w2=pack2(wr[128]), w3=pack2(wr[192]);
            acc[0][0]=fma2(ap0,w0,acc[0][0]); acc[0][1]=fma2(ap0,w1,acc[0][1]);
            acc[0][2]=fma2(ap0,w2,acc[0][2]); acc[0][3]=fma2(ap0,w3,acc[0][3]);
            acc[1][0]=fma2(ap1,w0,acc[1][0]); acc[1][1]=fma2(ap1,w1,acc[1][1]);
            acc[1][2]=fma2(ap1,w2,acc[1][2]); acc[1][3]=fma2(ap1,w3,acc[1][3]);
            acc[2][0]=fma2(ap2,w0,acc[2][0]); acc[2][1]=fma2(ap2,w1,acc[2][1]);
            acc[2][2]=fma2(ap2,w2,acc[2][2]); acc[2][3]=fma2(ap2,w3,acc[2][3]);
            acc[3][0]=fma2(ap3,w0,acc[3][0]); acc[3][1]=fma2(ap3,w1,acc[3][1]);
            acc[3][2]=fma2(ap3,w2,acc[3][2]); acc[3][3]=fma2(ap3,w3,acc[3][3]);
        }
        if (more){
            const int bo = ((c+1)&1);
            if (aok){
                float* d = sA + bo*KC*64;
                d[(akq*4+0)*64+am]=ra.x; d[(akq*4+1)*64+am]=ra.y;
                d[(akq*4+2)*64+am]=ra.z; d[(akq*4+3)*64+am]=ra.w;
            }
            if (wkm){
                float* d = sW + bo*KC*256;
                *reinterpret_cast<float4*>(d + kk*256 + col4)     = rw0;
                *reinterpret_cast<float4*>(d + (kk+8)*256 + col4) = rw1;
            } else {
                float* d = sW + bo*KC*256;
                d[(kq0*4+0)*256+wn]=rw0.x; d[(kq0*4+1)*256+wn]=rw0.y;
                d[(kq0*4+2)*256+wn]=rw0.z; d[(kq0*4+3)*256+wn]=rw0.w;
                d[(kq0*4+4)*256+wn]=rw1.x; d[(kq0*4+5)*256+wn]=rw1.y;
                d[(kq0*4+6)*256+wn]=rw1.z; d[(kq0*4+7)*256+wn]=rw1.w;
            }
        }
        __syncthreads();
    }

#pragma unroll
    for (int p=0;p<4;p++){
        const int r0 = ty*8 + 2*p;
#pragma unroll
        for (int j=0;j<4;j++){
            const int col = tx + 64*j;
            if (col < wcols){
                float lo = lo32(acc[p][j]), hi = hi32(acc[p][j]);
                if (epi == 1){ float b = bias[col]; lo += b; hi += b; }
                else if (epi == 2){ float b = bias[col]; lo = tanhf(lo+b); hi = tanhf(hi+b); }
                C[(size_t)r0*ldc + col]     = lo;
                C[(size_t)(r0+1)*ldc + col] = hi;
            }
        }
    }
}

// ---------------- attention + gi_r task (one batch per CTA) ----------------
__device__ void attn_task(int b, int cu, float* sm)
{
    float* sq  = sm;         // 512
    float* sal = sm + 512;   // 64
    const int tid = threadIdx.x;
    const int w = tid>>5, lane = tid&31;

    sq[tid] = g_s[cu][b*512 + tid];
    __syncthreads();

#pragma unroll
    for (int i=0;i<4;i++){
        const int n = w*4 + i;
        const float* kp = &g_kp[((size_t)b*64 + n)*512];
        float acc = 0.f;
#pragma unroll
        for (int c=0;c<4;c++){
            float4 kv = ld4(kp + c*128 + lane*4);
            float4 qv = ld4(sq + c*128 + lane*4);
            acc = fmaf(kv.x,qv.x,acc); acc = fmaf(kv.y,qv.y,acc);
            acc = fmaf(kv.z,qv.z,acc); acc = fmaf(kv.w,qv.w,acc);
        }
#pragma unroll
        for (int o=16;o>0;o>>=1) acc += __shfl_down_sync(0xffffffffu, acc, o);
        if (lane==0) sal[n] = acc + g_c0[b*64+n];
    }
    __syncthreads();

    if (w==0){
        float x0 = sal[lane], x1 = sal[lane+32];
        float m = fmaxf(x0,x1);
#pragma unroll
        for (int o=16;o>0;o>>=1) m = fmaxf(m, __shfl_xor_sync(0xffffffffu, m, o));
        float e0 = expf(x0-m), e1 = expf(x1-m);
        float s = e0+e1;
#pragma unroll
        for (int o=16;o>0;o>>=1) s += __shfl_xor_sync(0xffffffffu, s, o);
        float inv = 1.f/s;
        sal[lane] = e0*inv; sal[lane+32] = e1*inv;
    }
    __syncthreads();

    // r = alpha @ v
    {
        const float* vb = g_v + (size_t)b*64*512 + tid;
        float a0=0.f,a1=0.f,a2=0.f,a3=0.f;
#pragma unroll 4
        for (int n=0;n<64;n+=4){
            a0 = fmaf(sal[n+0], vb[(size_t)(n+0)*512], a0);
            a1 = fmaf(sal[n+1], vb[(size_t)(n+1)*512], a1);
            a2 = fmaf(sal[n+2], vb[(size_t)(n+2)*512], a2);
            a3 = fmaf(sal[n+3], vb[(size_t)(n+3)*512], a3);
        }
        g_r[cu][b*512+tid] = (a0+a1)+(a2+a3);
    }
    // gi_r = alpha @ V'
#pragma unroll
    for (int h=0;h<3;h++){
        const int j = h*512 + tid;
        const float* vp = g_vp + (size_t)b*64*1536 + j;
        float a0=0.f,a1=0.f;
#pragma unroll 4
        for (int n=0;n<64;n+=2){
            a0 = fmaf(sal[n+0], vp[(size_t)(n+0)*1536], a0);
            a1 = fmaf(sal[n+1], vp[(size_t)(n+1)*1536], a1);
        }
        g_gir[b*1536+j] = a0+a1;
    }
}

// ---------------- combine task ----------------
__device__ void combine_task(int b, int u,
                             const float* __restrict__ grep,
                             const float* __restrict__ b_hh,
                             const float* __restrict__ w_loc,
                             const float* __restrict__ b_loc,
                             float* sm)
{
    const int j = threadIdx.x;
    const int base = b*1536;
    const int cu = u&1;

    float ir  = g_gig[base+j]      + g_gir[base+j];
    float iz  = g_gig[base+512+j]  + g_gir[base+512+j];
    float inn = g_gig[base+1024+j] + g_gir[base+1024+j];
    float hr = b_hh[j], hz = b_hh[512+j], hn = b_hh[1024+j];
#pragma unroll
    for (int p=0;p<8;p++){
        const float* gp = &g_ghp[p][base];
        hr += gp[j]; hz += gp[512+j]; hn += gp[1024+j];
    }
    float rg = 1.f/(1.f+expf(-(ir+hr)));
    float zg = 1.f/(1.f+expf(-(iz+hz)));
    float ng = tanhf(inn + rg*hn);
    float so = g_s[cu][b*512+j];
    float sn = (1.f-zg)*ng + zg*so;
    g_s[cu^1][b*512+j] = sn;

    float rr = g_r[cu][b*512+j], gg = grep[b*512+j];
    float p0 = sn*w_loc[j]      + rr*w_loc[512+j]  + gg*w_loc[1024+j];
    float p1 = sn*w_loc[1536+j] + rr*w_loc[2048+j] + gg*w_loc[2560+j];

    const int warp = j>>5, lane = j&31;
#pragma unroll
    for (int o=16;o>0;o>>=1){
        p0 += __shfl_xor_sync(0xffffffffu, p0, o);
        p1 += __shfl_xor_sync(0xffffffffu, p1, o);
    }
    if (lane==0){ sm[warp]=p0; sm[16+warp]=p1; }
    __syncthreads();
    if (j==0){
        float l0=b_loc[0], l1=b_loc[1];
#pragma unroll
        for (int w=0;w<16;w++){ l0+=sm[w]; l1+=sm[16+w]; }
        float cx = tanhf(l0), cy = tanhf(l1);
        int jx = (int)rintf(0.5f*(cx+1.f)*127.f);
        int iy = (int)rintf(0.5f*(cy+1.f)*127.f);
        jx = min(127, max(0, jx));
        iy = min(127, max(0, iy));
        g_ij[cu][b*2]   = iy;
        g_ij[cu][b*2+1] = jx;
    }
}

// ---------------- scatter task ----------------
__device__ void scatter_task(int b, int par, const float* __restrict__ b_write,
                             float* __restrict__ out)
{
    const int c = threadIdx.x;
    if (c >= 400) return;
    const int iy = g_ij[par][b*2], jx = g_ij[par][b*2+1];
    float v = b_write[c];
#pragma unroll
    for (int p=0;p<16;p++) v += g_pp[p][b*512+c];
    int ch = c/25, rem = c - ch*25;
    int ki = rem/5, kj = rem - ki*5;
    int row = iy + ki - 2, col = jx + kj - 2;
    if ((unsigned)row < 128u && (unsigned)col < 128u){
        size_t o = (((size_t)b*16 + ch)*128 + row)*128 + col;
        out[o] += v;
    }
}

// ---------------- persistent kernel ----------------
__global__ void __launch_bounds__(NT,1) painter(
    const float* __restrict__ tok,    const float* __restrict__ grep,
    const int*   __restrict__ mask,
    const float* __restrict__ w_init, const float* __restrict__ b_init,
    const float* __restrict__ wq,     const float* __restrict__ bq,
    const float* __restrict__ wk,     const float* __restrict__ bk,
    const float* __restrict__ wv,     const float* __restrict__ bv,
    const float* __restrict__ w_ih,   const float* __restrict__ b_ih,
    const float* __restrict__ w_hh,   const float* __restrict__ b_hh,
    const float* __restrict__ w_write,const float* __restrict__ b_write,
    const float* __restrict__ w_loc,  const float* __restrict__ b_loc,
    float* __restrict__ out, int out_n)
{
    __shared__ float sh[2*KC*64 + 2*KC*256];   // 40KB
    float* sA = sh;
    float* sW = sh + 2*KC*64;
    const int bid = blockIdx.x, tid = threadIdx.x;

    // ---- P0: k_tok, v_tok, s0, gi_g, zero canvas ----
    for (int task=bid; task<328; task+=GRID){
        if (task < 256){
            int mat = task>>7, rem = task&127;
            int m0 = (rem>>1)*64, n0 = (rem&1)*256;
            gemm_t(tok + (size_t)m0*512, 512,
                   (mat?wv:wk) + (size_t)n0*512, 512, 0, 32, 256,
                   (mat?g_v:g_k) + (size_t)m0*512 + n0, 512,
                   (mat?bv:bk)+n0, 1, sA, sW);
        } else if (task < 258){
            int n0 = (task-256)*256;
            gemm_t(grep, 512, w_init + (size_t)n0*512, 512, 0, 32, 256,
                   g_s[0]+n0, 512, b_init+n0, 2, sA, sW);
        } else if (task < 264){
            int n0 = (task-258)*256;
            gemm_t(grep, 512, w_ih + (size_t)n0*1024 + 512, 1024, 0, 32, 256,
                   g_gig+n0, 1536, b_ih+n0, 1, sA, sW);
        } else {
            int z = task-264;                 // 0..63
            int per4 = (out_n>>2)/64;
            float4* p = reinterpret_cast<float4*>(out) + (size_t)z*per4;
            for (int i=tid;i<per4;i+=NT) p[i] = make_float4(0.f,0.f,0.f,0.f);
        }
    }
    gsync();

    // ---- P1: K' (128), V' (384), c0 (256) ----
    for (int task=bid; task<768; task+=GRID){
        if (task < 128){
            int m0 = (task>>1)*64, n0 = (task&1)*256;
            gemm_t(g_k + (size_t)m0*512, 512, wq + n0, 512, 1, 32, 256,
                   g_kp + (size_t)m0*512 + n0, 512, 0, 0, sA, sW);
        } else if (task < 512){
            int id = task-128;
            int m0 = (id/6)*64, n0 = (id%6)*256;
            gemm_t(g_v + (size_t)m0*512, 512, w_ih + (size_t)n0*1024, 1024, 0, 32, 256,
                   g_vp + (size_t)m0*1536 + n0, 1536, 0, 0, sA, sW);
        } else {
            int w = tid>>5, lane = tid&31;
            int row = (task-512)*16 + w;
            const float* kp = &g_k[(size_t)row*512];
            float acc = 0.f;
#pragma unroll
            for (int c=0;c<4;c++){
                float4 kv = ld4(kp + c*128 + lane*4);
                float4 bv4 = ld4(bq + c*128 + lane*4);
                acc = fmaf(kv.x,bv4.x,acc); acc = fmaf(kv.y,bv4.y,acc);
                acc = fmaf(kv.z,bv4.z,acc); acc = fmaf(kv.w,bv4.w,acc);
            }
#pragma unroll
            for (int o=16;o>0;o>>=1) acc += __shfl_down_sync(0xffffffffu, acc, o);
            if (lane==0) g_c0[row] = (mask[row]==0) ? -1e9f : acc;
        }
    }
    gsync();

    // ---- 33 pipelined iterations, 2 phases each ----
    for (int u=0; u<=32; u++){
        const int cu = u&1;

        // Phase A: gh(48,u<32) + patch_{u-1}(32,u>0) + attn(64,u<32)
        for (int task=bid; task<144; task+=GRID){
            if (task < 48){
                if (u < 32){
                    int n0 = (task%6)*256, kp = task/6;
                    gemm_t(g_s[cu] + kp*64, 512,
                           w_hh + (size_t)n0*512 + kp*64, 512, 0, 4, 256,
                           g_ghp[kp]+n0, 1536, 0, 0, sA, sW);
                }
            } else if (task < 80){
                if (u > 0){
                    int id = task-48;
                    int nt = id&1, kp = id>>1;
                    int n0 = nt*256;
                    const float* Ab = (kp<8) ? (g_s[cu] + kp*64)
                                             : (g_r[(u-1)&1] + (kp-8)*64);
                    gemm_t(Ab, 512, w_write + (size_t)n0*1024 + kp*64, 1024, 0, 4,
                           nt ? 144 : 256, g_pp[kp]+n0, 512, 0, 0, sA, sW);
                }
            } else {
                if (u < 32) attn_task(task-80, cu, sh);
            }
        }
        gsync();

        // Phase B: combine(64,u<32) + scatter_{u-1}(64,u>0)
        for (int task=bid; task<128; task+=GRID){
            if (task < 64){
                if (u < 32) combine_task(task, u, grep, b_hh, w_loc, b_loc, sh);
            } else {
                if (u > 0) scatter_task(task-64, (u-1)&1, b_write, out);
            }
        }
        gsync();
    }
}

// ---------------- launch ----------------
extern "C" void kernel_launch(void* const* d_in, const int* in_sizes, int n_in,
                              void* d_out, int out_size)
{
    const float* token_reps = (const float*)d_in[0];
    const float* global_rep = (const float*)d_in[1];
    const int*   mask       = (const int*)  d_in[2];
    const float* w_init     = (const float*)d_in[3];
    const float* b_init     = (const float*)d_in[4];
    const float* wq         = (const float*)d_in[5];
    const float* bq         = (const float*)d_in[6];
    const float* wk         = (const float*)d_in[7];
    const float* bk         = (const float*)d_in[8];
    const float* wv         = (const float*)d_in[9];
    const float* bv         = (const float*)d_in[10];
    const float* w_ih       = (const float*)d_in[11];
    const float* b_ih       = (const float*)d_in[12];
    const float* w_hh       = (const float*)d_in[13];
    const float* b_hh       = (const float*)d_in[14];
    const float* w_write    = (const float*)d_in[15];
    const float* b_write    = (const float*)d_in[16];
    const float* w_loc      = (const float*)d_in[17];
    const float* b_loc      = (const float*)d_in[18];

    painter<<<GRID, NT>>>(token_reps, global_rep, mask,
                          w_init, b_init, wq, bq, wk, bk, wv, bv,
                          w_ih, b_ih, w_hh, b_hh, w_write, b_write,
                          w_loc, b_loc, (float*)d_out, out_size);
}